// round 10
// baseline (speedup 1.0000x reference)
#include <cuda_runtime.h>

#define BB 32
#define RR 512
#define TT 128
#define HH 64

typedef unsigned long long ull;

// ---- scratch (device globals; no allocations) ----
__device__ float g_k  [BB*RR*HH];
__device__ float g_v  [BB*RR*HH];
__device__ float g_rpT[BB*HH*RR];   // transposed: [b][k][r]
__device__ float g_q  [BB*TT*HH];
__device__ float g_tp [BB*TT*HH];

// ---- packed fp32x2 helpers (Blackwell FFMA2 path) ----
__device__ __forceinline__ void fma2(ull& d, ull a, ull b) {
    asm("fma.rn.f32x2 %0, %1, %2, %0;" : "+l"(d) : "l"(a), "l"(b));
}
__device__ __forceinline__ float2 unpack2(ull v) {
    float2 f;
    asm("mov.b64 {%0, %1}, %2;" : "=f"(f.x), "=f"(f.y) : "l"(v));
    return f;
}

// =====================================================================
// Kernel 1: merged encoders.
// blocks [0,512): robot encoder + K,V,rpT projections (32 rows/block)
// blocks [512,1024): task encoder + Q projection (8 rows/block)
// =====================================================================
__global__ void __launch_bounds__(256) k_enc(
    const float* __restrict__ xr_, const float* __restrict__ xt_,
    const float* __restrict__ rw1, const float* __restrict__ rb1,
    const float* __restrict__ rw2, const float* __restrict__ rb2,
    const float* __restrict__ tw1, const float* __restrict__ tb1,
    const float* __restrict__ tw2, const float* __restrict__ tb2,
    const float* __restrict__ wq, const float* __restrict__ bq,
    const float* __restrict__ wk, const float* __restrict__ bk,
    const float* __restrict__ wv, const float* __restrict__ bv,
    const float* __restrict__ aw1)
{
    __shared__ float sA[8][4][64];
    __shared__ float sB[8][4][64];
    int wid = threadIdx.x >> 5, lane = threadIdx.x & 31;
    int c = lane * 2;

    if (blockIdx.x < 512) {
        // ---------------- robot path ----------------
        int r0 = blockIdx.x * 32 + wid * 4;
        const float* xp = xr_ + r0 * 7;
        float xv[4][7];
#pragma unroll
        for (int rr = 0; rr < 4; rr++)
#pragma unroll
            for (int i = 0; i < 7; i++) xv[rr][i] = xp[rr*7 + i];

        float2 b1v = *(const float2*)&rb1[c];
        float h[4][2];
#pragma unroll
        for (int rr = 0; rr < 4; rr++) { h[rr][0] = b1v.x; h[rr][1] = b1v.y; }
#pragma unroll
        for (int i = 0; i < 7; i++) {
            float2 w = *(const float2*)&rw1[i*64 + c];
#pragma unroll
            for (int rr = 0; rr < 4; rr++) { h[rr][0] += xv[rr][i]*w.x; h[rr][1] += xv[rr][i]*w.y; }
        }
#pragma unroll
        for (int rr = 0; rr < 4; rr++) {
            sA[wid][rr][c]   = fmaxf(h[rr][0], 0.f);
            sA[wid][rr][c+1] = fmaxf(h[rr][1], 0.f);
        }
        __syncwarp();

        float2 b2v = *(const float2*)&rb2[c];
        float g[4][2];
#pragma unroll
        for (int rr = 0; rr < 4; rr++) { g[rr][0] = b2v.x; g[rr][1] = b2v.y; }
#pragma unroll 4
        for (int j = 0; j < 64; j++) {
            float2 w = *(const float2*)&rw2[j*64 + c];
#pragma unroll
            for (int rr = 0; rr < 4; rr++) {
                float s = sA[wid][rr][j];
                g[rr][0] += s*w.x; g[rr][1] += s*w.y;
            }
        }
#pragma unroll
        for (int rr = 0; rr < 4; rr++) {
            sB[wid][rr][c]   = fmaxf(g[rr][0], 0.f);
            sB[wid][rr][c+1] = fmaxf(g[rr][1], 0.f);
        }
        __syncwarp();

        float2 bkv = *(const float2*)&bk[c];
        float2 bvv = *(const float2*)&bv[c];
        float ka[4][2], va[4][2], pa[4][2];
#pragma unroll
        for (int rr = 0; rr < 4; rr++) {
            ka[rr][0] = bkv.x; ka[rr][1] = bkv.y;
            va[rr][0] = bvv.x; va[rr][1] = bvv.y;
            pa[rr][0] = 0.f;   pa[rr][1] = 0.f;
        }
#pragma unroll 2
        for (int j = 0; j < 64; j++) {
            float2 wkj = *(const float2*)&wk[j*64 + c];
            float2 wvj = *(const float2*)&wv[j*64 + c];
            float2 waj = *(const float2*)&aw1[(64+j)*64 + c];
#pragma unroll
            for (int rr = 0; rr < 4; rr++) {
                float s = sB[wid][rr][j];
                ka[rr][0] += s*wkj.x; ka[rr][1] += s*wkj.y;
                va[rr][0] += s*wvj.x; va[rr][1] += s*wvj.y;
                pa[rr][0] += s*waj.x; pa[rr][1] += s*waj.y;
            }
        }
#pragma unroll
        for (int rr = 0; rr < 4; rr++) {
            int gr = r0 + rr;
            *(float2*)&g_k[gr*64 + c] = make_float2(ka[rr][0], ka[rr][1]);
            *(float2*)&g_v[gr*64 + c] = make_float2(va[rr][0], va[rr][1]);
            int bb = gr >> 9, rloc = gr & 511;
            g_rpT[((size_t)bb*64 + c  )*512 + rloc] = pa[rr][0];
            g_rpT[((size_t)bb*64 + c+1)*512 + rloc] = pa[rr][1];
        }
    } else {
        // ---------------- task path ----------------
        int row = (blockIdx.x - 512) * 8 + wid;
        const float* xr = xt_ + row * 6;
        float xv[6];
#pragma unroll
        for (int i = 0; i < 6; i++) xv[i] = xr[i];

        float ha = tb1[c], hb = tb1[c+1];
#pragma unroll
        for (int i = 0; i < 6; i++) {
            float2 w = *(const float2*)&tw1[i*64 + c];
            ha += xv[i]*w.x; hb += xv[i]*w.y;
        }
        sA[wid][0][c] = fmaxf(ha, 0.f); sA[wid][0][c+1] = fmaxf(hb, 0.f);
        __syncwarp();

        float ga = tb2[c], gb = tb2[c+1];
#pragma unroll 8
        for (int j = 0; j < 64; j++) {
            float2 w = *(const float2*)&tw2[j*64 + c];
            float s = sA[wid][0][j];
            ga += s*w.x; gb += s*w.y;
        }
        sB[wid][0][c] = fmaxf(ga, 0.f); sB[wid][0][c+1] = fmaxf(gb, 0.f);
        __syncwarp();

        float qa = bq[c], qb = bq[c+1];
#pragma unroll 8
        for (int j = 0; j < 64; j++) {
            float2 w = *(const float2*)&wq[j*64 + c];
            float s = sB[wid][0][j];
            qa += s*w.x; qb += s*w.y;
        }
        g_q[row*64 + c] = qa; g_q[row*64 + c+1] = qb;
    }
}

// =====================================================================
// Kernel 3: attention, 8 tasks per block (grid = B*16 = 512), 256 thr
// =====================================================================
#define AQ   0
#define ALG  512
#define AKV  16896
#define AINV 25600
#define ACS  25632
#define ATF  26144
#define ATTN_SMEM_FLOATS 26656

__global__ void __launch_bounds__(256) k_attn(
    const float* __restrict__ wo, const float* __restrict__ bo,
    const float* __restrict__ aw1, const float* __restrict__ ab1)
{
    extern __shared__ float sm[];
    int blk = blockIdx.x;
    int b = blk >> 4;
    int tk0 = (blk & 15) * 8;
    int t = threadIdx.x, lane = t & 31, w = t >> 5;

    for (int i = t; i < 512; i += 256)
        sm[AQ + i] = g_q[(size_t)(b*128 + tk0 + (i >> 6))*64 + (i & 63)];

    const float* kb = g_k + (size_t)b*RR*64;
    const float* vb = g_v + (size_t)b*RR*64;

    for (int chunk = 0; chunk < 4; chunk++) {
        __syncthreads();
#pragma unroll
        for (int i = 0; i < 8; i++) {
            int lin = t + i*256;
            int row = lin >> 4, c4 = lin & 15;
            float4 kvv = *(const float4*)(kb + (size_t)(chunk*128 + row)*64 + c4*4);
            *(float4*)&sm[AKV + row*68 + c4*4] = kvv;
        }
        __syncthreads();
#pragma unroll
        for (int i = 0; i < 16; i++) {
            int idx = i*256 + t;
            int th = idx >> 7, r = idx & 127;
            int task = th >> 2, h = th & 3;
            const float* kr = &sm[AKV + r*68 + h*16];
            const float* qh = &sm[AQ + task*64 + h*16];
            float d = 0.f;
#pragma unroll
            for (int j = 0; j < 16; j += 4) {
                float4 kv4 = *(const float4*)(kr + j);
                float4 q4  = *(const float4*)(qh + j);
                d += kv4.x*q4.x + kv4.y*q4.y + kv4.z*q4.z + kv4.w*q4.w;
            }
            sm[ALG + (task*4 + h)*512 + chunk*128 + r] = d * 0.25f;
        }
    }
    __syncthreads();

    for (int p = w; p < 32; p += 8) {
        float* base = &sm[ALG + p*512];
        float v[16];
        float m = -1e30f;
#pragma unroll
        for (int i = 0; i < 16; i++) { v[i] = base[i*32 + lane]; m = fmaxf(m, v[i]); }
#pragma unroll
        for (int o = 16; o; o >>= 1) m = fmaxf(m, __shfl_xor_sync(0xffffffffu, m, o));
        float s = 0.f;
#pragma unroll
        for (int i = 0; i < 16; i++) {
            float e = __expf(v[i] - m);
            base[i*32 + lane] = e;
            s += e;
        }
#pragma unroll
        for (int o = 16; o; o >>= 1) s += __shfl_xor_sync(0xffffffffu, s, o);
        if (lane == 0) sm[AINV + p] = 1.f / s;
    }
    __syncthreads();

    int task = t >> 5;
    int c2 = (t & 31) * 2;
    int hh = c2 >> 4;
    float acc0 = 0.f, acc1 = 0.f;
    for (int chunk = 0; chunk < 4; chunk++) {
        __syncthreads();
#pragma unroll
        for (int i = 0; i < 8; i++) {
            int lin = t + i*256;
            int row = lin >> 4, c4 = lin & 15;
            float4 vvv = *(const float4*)(vb + (size_t)(chunk*128 + row)*64 + c4*4);
            *(float4*)&sm[AKV + row*68 + c4*4] = vvv;
        }
        __syncthreads();
        const float* lgp = &sm[ALG + (task*4 + hh)*512 + chunk*128];
#pragma unroll 4
        for (int r = 0; r < 128; r++) {
            float a = lgp[r];
            float2 vv = *(const float2*)&sm[AKV + r*68 + c2];
            acc0 += a*vv.x; acc1 += a*vv.y;
        }
    }
    __syncthreads();

    {
        float inv = sm[AINV + task*4 + hh];
        sm[ACS + task*64 + c2]     = acc0 * inv;
        sm[ACS + task*64 + c2 + 1] = acc1 * inv;
    }
#pragma unroll
    for (int i = 0; i < 4; i++) {
        int lin = t + i*256;
        *(float4*)&sm[AKV + lin*4]        = *(const float4*)(wo  + lin*4);
        *(float4*)&sm[AKV + 4096 + lin*4] = *(const float4*)(aw1 + lin*4);
    }
    __syncthreads();

    {
        int c = lane * 2;
        float2 bov = *(const float2*)&bo[c];
        float f0 = bov.x, f1 = bov.y;
#pragma unroll 8
        for (int j = 0; j < 64; j++) {
            float s = sm[ACS + w*64 + j];
            float2 ww = *(const float2*)&sm[AKV + j*64 + c];
            f0 += s*ww.x; f1 += s*ww.y;
        }
        sm[ATF + w*64 + c] = f0; sm[ATF + w*64 + c + 1] = f1;
        __syncwarp();
        float2 abv = *(const float2*)&ab1[c];
        float p0 = abv.x, p1 = abv.y;
#pragma unroll 8
        for (int j = 0; j < 64; j++) {
            float s = sm[ATF + w*64 + j];
            float2 ww = *(const float2*)&sm[AKV + 4096 + j*64 + c];
            p0 += s*ww.x; p1 += s*ww.y;
        }
        *(float2*)&g_tp[(size_t)(b*128 + tk0 + w)*64 + c] = make_float2(p0, p1);
    }
}

// =====================================================================
// Kernel 4 (dominant): pairwise MLP + softmax. block per (b,t), 128 thr
// 4 tiles of 128 robots; h1 TRANSPOSED h1T[k][r]; fp32x2 packs two
// adjacent robot rows. W2/b2 duplicated in smem.
// launch_bounds(128, 3): reg budget 170 -> NO SPILLS (the (128,4) cap
// of rounds 7-8 forced hot-loop local-memory spills = 2.6x regression).
// =====================================================================
#define QW2D 0
#define QB2D 4096
#define QW3  4160
#define QTPS 4192
#define QH1T 4256
#define QSP  12704
#define QSC  13232
#define QRED 13744
#define PAIR_SMEM_FLOATS 13752

__global__ void __launch_bounds__(128, 3) k_pair(
    const float* __restrict__ aw2, const float* __restrict__ ab2,
    const float* __restrict__ aw3, float* __restrict__ out)
{
    extern __shared__ float sm[];
    int bt = blockIdx.x;
    int b  = bt >> 7;
    int t = threadIdx.x, lane = t & 31, wid = t >> 5;

    // stage duplicated W2 / b2, w3, tp
    for (int i = t; i < 2048; i += 128) {
        float v = aw2[i];
        int k = i >> 5, cc = i & 31;
        sm[QW2D + k*64 + 2*cc]     = v;
        sm[QW2D + k*64 + 2*cc + 1] = v;
    }
    if (t < 32) {
        float v = ab2[t];
        sm[QB2D + 2*t] = v; sm[QB2D + 2*t + 1] = v;
        sm[QW3 + t] = aw3[t];
    }
    if (t < 64) sm[QTPS + t] = g_tp[bt*64 + t];
    __syncthreads();

    int tx = t & 3;          // col group: cols tx*8..tx*8+7
    int ty = t >> 2;         // 0..31 -> rows 4ty..4ty+3 (2 fp32x2 pairs)
    int q  = t & 31;         // build: robot quad
    int kw = t >> 5;         // build: k row base
    const float* rpT = g_rpT + (size_t)b*64*512;

    for (int tile = 0; tile < 4; tile++) {
        int r0 = tile * 128;
        // ---- build h1T[k][r] = relu(tp[k] + rpT[k][r]) ----
#pragma unroll 4
        for (int i = 0; i < 16; i++) {
            int k = kw + 4*i;
            float tpk = sm[QTPS + k];
            float4 rv = *(const float4*)(rpT + (size_t)k*512 + r0 + 4*q);
            float4 hv;
            hv.x = fmaxf(rv.x + tpk, 0.f);
            hv.y = fmaxf(rv.y + tpk, 0.f);
            hv.z = fmaxf(rv.z + tpk, 0.f);
            hv.w = fmaxf(rv.w + tpk, 0.f);
            *(float4*)&sm[QH1T + k*132 + 4*q] = hv;
        }
        __syncthreads();

        // ---- GEMM: rows 4ty..4ty+3 (2 packed pairs) x cols tx*8..+7 ----
        ull acc0[8], acc1[8];
#pragma unroll
        for (int cc = 0; cc < 8; cc++) {
            ull bv = *(const ull*)&sm[QB2D + 2*(tx*8 + cc)];
            acc0[cc] = bv; acc1[cc] = bv;
        }
        {
            const float* h1p = &sm[QH1T + 4*ty];
            const float* w2p = &sm[QW2D + tx*16];
#pragma unroll 2
            for (int k = 0; k < 64; k++) {
                ulonglong2 av = *(const ulonglong2*)(h1p + k*132);
                const ulonglong2* wp = (const ulonglong2*)(w2p + k*64);
                {
                    ulonglong2 wA = wp[0];
                    fma2(acc0[0], av.x, wA.x); fma2(acc1[0], av.y, wA.x);
                    fma2(acc0[1], av.x, wA.y); fma2(acc1[1], av.y, wA.y);
                }
                {
                    ulonglong2 wB = wp[1];
                    fma2(acc0[2], av.x, wB.x); fma2(acc1[2], av.y, wB.x);
                    fma2(acc0[3], av.x, wB.y); fma2(acc1[3], av.y, wB.y);
                }
                {
                    ulonglong2 wC = wp[2];
                    fma2(acc0[4], av.x, wC.x); fma2(acc1[4], av.y, wC.x);
                    fma2(acc0[5], av.x, wC.y); fma2(acc1[5], av.y, wC.y);
                }
                {
                    ulonglong2 wD = wp[3];
                    fma2(acc0[6], av.x, wD.x); fma2(acc1[6], av.y, wD.x);
                    fma2(acc0[7], av.x, wD.y); fma2(acc1[7], av.y, wD.y);
                }
            }
        }

        // ---- epilogue: relu(h2) . a_w3 -> 4 row scores ----
        float s00 = 0.f, s01 = 0.f, s10 = 0.f, s11 = 0.f;
#pragma unroll
        for (int cc = 0; cc < 8; cc++) {
            float w3v = sm[QW3 + tx*8 + cc];
            float2 f0 = unpack2(acc0[cc]);
            float2 f1 = unpack2(acc1[cc]);
            s00 += fmaxf(f0.x, 0.f) * w3v;
            s01 += fmaxf(f0.y, 0.f) * w3v;
            s10 += fmaxf(f1.x, 0.f) * w3v;
            s11 += fmaxf(f1.y, 0.f) * w3v;
        }
        sm[QSP + tx*132 + 4*ty]     = s00;
        sm[QSP + tx*132 + 4*ty + 1] = s01;
        sm[QSP + tx*132 + 4*ty + 2] = s10;
        sm[QSP + tx*132 + 4*ty + 3] = s11;
        __syncthreads();
        sm[QSC + r0 + t] = sm[QSP + t] + sm[QSP + 132 + t] + sm[QSP + 264 + t] + sm[QSP + 396 + t];
        __syncthreads();
    }

    // ---- softmax over 512 robots ----
    float v0 = sm[QSC + t], v1 = sm[QSC + t + 128], v2 = sm[QSC + t + 256], v3 = sm[QSC + t + 384];
    float m = fmaxf(fmaxf(v0, v1), fmaxf(v2, v3));
#pragma unroll
    for (int o = 16; o; o >>= 1) m = fmaxf(m, __shfl_xor_sync(0xffffffffu, m, o));
    if (lane == 0) sm[QRED + wid] = m;
    __syncthreads();
    m = fmaxf(fmaxf(sm[QRED + 0], sm[QRED + 1]), fmaxf(sm[QRED + 2], sm[QRED + 3]));
    v0 = __expf(v0 - m); v1 = __expf(v1 - m); v2 = __expf(v2 - m); v3 = __expf(v3 - m);
    float s = v0 + v1 + v2 + v3;
#pragma unroll
    for (int o = 16; o; o >>= 1) s += __shfl_xor_sync(0xffffffffu, s, o);
    if (lane == 0) sm[QRED + 4 + wid] = s;
    __syncthreads();
    s = sm[QRED + 4] + sm[QRED + 5] + sm[QRED + 6] + sm[QRED + 7];
    float inv = 1.f / s;
    float* op = out + (size_t)bt * 512;
    op[t]     = v0 * inv;
    op[t+128] = v1 * inv;
    op[t+256] = v2 * inv;
    op[t+384] = v3 * inv;
}

// =====================================================================
extern "C" void kernel_launch(void* const* d_in, const int* in_sizes, int n_in,
                              void* d_out, int out_size)
{
    (void)in_sizes; (void)n_in; (void)out_size;
    const float* robot = (const float*)d_in[0];
    const float* task  = (const float*)d_in[1];
    const float* r_w1  = (const float*)d_in[2];
    const float* r_b1  = (const float*)d_in[3];
    const float* r_w2  = (const float*)d_in[4];
    const float* r_b2  = (const float*)d_in[5];
    const float* t_w1  = (const float*)d_in[6];
    const float* t_b1  = (const float*)d_in[7];
    const float* t_w2  = (const float*)d_in[8];
    const float* t_b2  = (const float*)d_in[9];
    const float* wq    = (const float*)d_in[10];
    const float* bq    = (const float*)d_in[11];
    const float* wk    = (const float*)d_in[12];
    const float* bk    = (const float*)d_in[13];
    const float* wv    = (const float*)d_in[14];
    const float* bv    = (const float*)d_in[15];
    const float* wo    = (const float*)d_in[16];
    const float* bo    = (const float*)d_in[17];
    const float* a_w1  = (const float*)d_in[18];
    const float* a_b1  = (const float*)d_in[19];
    const float* a_w2  = (const float*)d_in[20];
    const float* a_b2  = (const float*)d_in[21];
    const float* a_w3  = (const float*)d_in[22];

    static_assert(ATTN_SMEM_FLOATS * 4 < 230000, "attn smem");
    static_assert(PAIR_SMEM_FLOATS * 4 < 58000, "pair smem");
    cudaFuncSetAttribute(k_attn, cudaFuncAttributeMaxDynamicSharedMemorySize, ATTN_SMEM_FLOATS * 4);
    cudaFuncSetAttribute(k_pair, cudaFuncAttributeMaxDynamicSharedMemorySize, PAIR_SMEM_FLOATS * 4);

    k_enc <<<1024, 256>>>(robot, task, r_w1, r_b1, r_w2, r_b2,
                          t_w1, t_b1, t_w2, t_b2, wq, bq, wk, bk, wv, bv, a_w1);
    k_attn<<<BB*16, 256, ATTN_SMEM_FLOATS * 4>>>(wo, bo, a_w1, a_b1);
    k_pair<<<BB*TT, 128, PAIR_SMEM_FLOATS * 4>>>(a_w2, a_b2, a_w3, (float*)d_out);
}

// round 12
// speedup vs baseline: 2.0604x; 2.0604x over previous
#include <cuda_runtime.h>

#define BB 32
#define RR 512
#define TT 128
#define HH 64

typedef unsigned long long ull;

// ---- scratch (device globals; no allocations) ----
__device__ float g_k [BB*RR*HH];
__device__ float g_v [BB*RR*HH];
__device__ float g_rp[BB*RR*HH];
__device__ float g_q [BB*TT*HH];
__device__ float g_tp[BB*TT*HH];

// ---- packed fp32x2 helpers (Blackwell FFMA2 path) ----
__device__ __forceinline__ ull pack2(float a) {
    ull r;
    asm("mov.b64 %0, {%1, %1};" : "=l"(r) : "f"(a));
    return r;
}
__device__ __forceinline__ void fma2(ull& d, ull a, ull b) {
    asm("fma.rn.f32x2 %0, %1, %2, %0;" : "+l"(d) : "l"(a), "l"(b));
}
__device__ __forceinline__ float2 unpack2(ull v) {
    float2 f;
    asm("mov.b64 {%0, %1}, %2;" : "=f"(f.x), "=f"(f.y) : "l"(v));
    return f;
}

// =====================================================================
// Kernel 1: merged encoders.
// blocks [0,512): robot encoder + K,V,rp projections (32 rows/block)
// blocks [512,1024): task encoder + Q projection (8 rows/block)
// =====================================================================
__global__ void __launch_bounds__(256) k_enc(
    const float* __restrict__ xr_, const float* __restrict__ xt_,
    const float* __restrict__ rw1, const float* __restrict__ rb1,
    const float* __restrict__ rw2, const float* __restrict__ rb2,
    const float* __restrict__ tw1, const float* __restrict__ tb1,
    const float* __restrict__ tw2, const float* __restrict__ tb2,
    const float* __restrict__ wq, const float* __restrict__ bq,
    const float* __restrict__ wk, const float* __restrict__ bk,
    const float* __restrict__ wv, const float* __restrict__ bv,
    const float* __restrict__ aw1)
{
    __shared__ float sA[8][4][64];
    __shared__ float sB[8][4][64];
    int wid = threadIdx.x >> 5, lane = threadIdx.x & 31;
    int c = lane * 2;

    if (blockIdx.x < 512) {
        // ---------------- robot path ----------------
        int r0 = blockIdx.x * 32 + wid * 4;
        const float* xp = xr_ + r0 * 7;
        float xv[4][7];
#pragma unroll
        for (int rr = 0; rr < 4; rr++)
#pragma unroll
            for (int i = 0; i < 7; i++) xv[rr][i] = xp[rr*7 + i];

        float2 b1v = *(const float2*)&rb1[c];
        float h[4][2];
#pragma unroll
        for (int rr = 0; rr < 4; rr++) { h[rr][0] = b1v.x; h[rr][1] = b1v.y; }
#pragma unroll
        for (int i = 0; i < 7; i++) {
            float2 w = *(const float2*)&rw1[i*64 + c];
#pragma unroll
            for (int rr = 0; rr < 4; rr++) { h[rr][0] += xv[rr][i]*w.x; h[rr][1] += xv[rr][i]*w.y; }
        }
#pragma unroll
        for (int rr = 0; rr < 4; rr++) {
            sA[wid][rr][c]   = fmaxf(h[rr][0], 0.f);
            sA[wid][rr][c+1] = fmaxf(h[rr][1], 0.f);
        }
        __syncwarp();

        float2 b2v = *(const float2*)&rb2[c];
        float g[4][2];
#pragma unroll
        for (int rr = 0; rr < 4; rr++) { g[rr][0] = b2v.x; g[rr][1] = b2v.y; }
#pragma unroll 4
        for (int j = 0; j < 64; j++) {
            float2 w = *(const float2*)&rw2[j*64 + c];
#pragma unroll
            for (int rr = 0; rr < 4; rr++) {
                float s = sA[wid][rr][j];
                g[rr][0] += s*w.x; g[rr][1] += s*w.y;
            }
        }
#pragma unroll
        for (int rr = 0; rr < 4; rr++) {
            sB[wid][rr][c]   = fmaxf(g[rr][0], 0.f);
            sB[wid][rr][c+1] = fmaxf(g[rr][1], 0.f);
        }
        __syncwarp();

        float2 bkv = *(const float2*)&bk[c];
        float2 bvv = *(const float2*)&bv[c];
        float ka[4][2], va[4][2], pa[4][2];
#pragma unroll
        for (int rr = 0; rr < 4; rr++) {
            ka[rr][0] = bkv.x; ka[rr][1] = bkv.y;
            va[rr][0] = bvv.x; va[rr][1] = bvv.y;
            pa[rr][0] = 0.f;   pa[rr][1] = 0.f;
        }
#pragma unroll 2
        for (int j = 0; j < 64; j++) {
            float2 wkj = *(const float2*)&wk[j*64 + c];
            float2 wvj = *(const float2*)&wv[j*64 + c];
            float2 waj = *(const float2*)&aw1[(64+j)*64 + c];
#pragma unroll
            for (int rr = 0; rr < 4; rr++) {
                float s = sB[wid][rr][j];
                ka[rr][0] += s*wkj.x; ka[rr][1] += s*wkj.y;
                va[rr][0] += s*wvj.x; va[rr][1] += s*wvj.y;
                pa[rr][0] += s*waj.x; pa[rr][1] += s*waj.y;
            }
        }
#pragma unroll
        for (int rr = 0; rr < 4; rr++) {
            int gr = r0 + rr;
            *(float2*)&g_k [gr*64 + c] = make_float2(ka[rr][0], ka[rr][1]);
            *(float2*)&g_v [gr*64 + c] = make_float2(va[rr][0], va[rr][1]);
            *(float2*)&g_rp[gr*64 + c] = make_float2(pa[rr][0], pa[rr][1]);
        }
    } else {
        // ---------------- task path ----------------
        int row = (blockIdx.x - 512) * 8 + wid;
        const float* xr = xt_ + row * 6;
        float xv[6];
#pragma unroll
        for (int i = 0; i < 6; i++) xv[i] = xr[i];

        float ha = tb1[c], hb = tb1[c+1];
#pragma unroll
        for (int i = 0; i < 6; i++) {
            float2 w = *(const float2*)&tw1[i*64 + c];
            ha += xv[i]*w.x; hb += xv[i]*w.y;
        }
        sA[wid][0][c] = fmaxf(ha, 0.f); sA[wid][0][c+1] = fmaxf(hb, 0.f);
        __syncwarp();

        float ga = tb2[c], gb = tb2[c+1];
#pragma unroll 8
        for (int j = 0; j < 64; j++) {
            float2 w = *(const float2*)&tw2[j*64 + c];
            float s = sA[wid][0][j];
            ga += s*w.x; gb += s*w.y;
        }
        sB[wid][0][c] = fmaxf(ga, 0.f); sB[wid][0][c+1] = fmaxf(gb, 0.f);
        __syncwarp();

        float qa = bq[c], qb = bq[c+1];
#pragma unroll 8
        for (int j = 0; j < 64; j++) {
            float2 w = *(const float2*)&wq[j*64 + c];
            float s = sB[wid][0][j];
            qa += s*w.x; qb += s*w.y;
        }
        g_q[row*64 + c] = qa; g_q[row*64 + c+1] = qb;
    }
}

// =====================================================================
// Kernel 3: attention, 8 tasks per block (grid = B*16 = 512), 256 thr
// =====================================================================
#define AQ   0
#define ALG  512
#define AKV  16896
#define AINV 25600
#define ACS  25632
#define ATF  26144
#define ATTN_SMEM_FLOATS 26656

__global__ void __launch_bounds__(256) k_attn(
    const float* __restrict__ wo, const float* __restrict__ bo,
    const float* __restrict__ aw1, const float* __restrict__ ab1)
{
    extern __shared__ float sm[];
    int blk = blockIdx.x;
    int b = blk >> 4;
    int tk0 = (blk & 15) * 8;
    int t = threadIdx.x, lane = t & 31, w = t >> 5;

    for (int i = t; i < 512; i += 256)
        sm[AQ + i] = g_q[(size_t)(b*128 + tk0 + (i >> 6))*64 + (i & 63)];

    const float* kb = g_k + (size_t)b*RR*64;
    const float* vb = g_v + (size_t)b*RR*64;

    for (int chunk = 0; chunk < 4; chunk++) {
        __syncthreads();
#pragma unroll
        for (int i = 0; i < 8; i++) {
            int lin = t + i*256;
            int row = lin >> 4, c4 = lin & 15;
            float4 kvv = *(const float4*)(kb + (size_t)(chunk*128 + row)*64 + c4*4);
            *(float4*)&sm[AKV + row*68 + c4*4] = kvv;
        }
        __syncthreads();
#pragma unroll
        for (int i = 0; i < 16; i++) {
            int idx = i*256 + t;
            int th = idx >> 7, r = idx & 127;
            int task = th >> 2, h = th & 3;
            const float* kr = &sm[AKV + r*68 + h*16];
            const float* qh = &sm[AQ + task*64 + h*16];
            float d = 0.f;
#pragma unroll
            for (int j = 0; j < 16; j += 4) {
                float4 kv4 = *(const float4*)(kr + j);
                float4 q4  = *(const float4*)(qh + j);
                d += kv4.x*q4.x + kv4.y*q4.y + kv4.z*q4.z + kv4.w*q4.w;
            }
            sm[ALG + (task*4 + h)*512 + chunk*128 + r] = d * 0.25f;
        }
    }
    __syncthreads();

    for (int p = w; p < 32; p += 8) {
        float* base = &sm[ALG + p*512];
        float v[16];
        float m = -1e30f;
#pragma unroll
        for (int i = 0; i < 16; i++) { v[i] = base[i*32 + lane]; m = fmaxf(m, v[i]); }
#pragma unroll
        for (int o = 16; o; o >>= 1) m = fmaxf(m, __shfl_xor_sync(0xffffffffu, m, o));
        float s = 0.f;
#pragma unroll
        for (int i = 0; i < 16; i++) {
            float e = __expf(v[i] - m);
            base[i*32 + lane] = e;
            s += e;
        }
#pragma unroll
        for (int o = 16; o; o >>= 1) s += __shfl_xor_sync(0xffffffffu, s, o);
        if (lane == 0) sm[AINV + p] = 1.f / s;
    }
    __syncthreads();

    int task = t >> 5;
    int c2 = (t & 31) * 2;
    int hh = c2 >> 4;
    float acc0 = 0.f, acc1 = 0.f;
    for (int chunk = 0; chunk < 4; chunk++) {
        __syncthreads();
#pragma unroll
        for (int i = 0; i < 8; i++) {
            int lin = t + i*256;
            int row = lin >> 4, c4 = lin & 15;
            float4 vvv = *(const float4*)(vb + (size_t)(chunk*128 + row)*64 + c4*4);
            *(float4*)&sm[AKV + row*68 + c4*4] = vvv;
        }
        __syncthreads();
        const float* lgp = &sm[ALG + (task*4 + hh)*512 + chunk*128];
#pragma unroll 4
        for (int r = 0; r < 128; r++) {
            float a = lgp[r];
            float2 vv = *(const float2*)&sm[AKV + r*68 + c2];
            acc0 += a*vv.x; acc1 += a*vv.y;
        }
    }
    __syncthreads();

    {
        float inv = sm[AINV + task*4 + hh];
        sm[ACS + task*64 + c2]     = acc0 * inv;
        sm[ACS + task*64 + c2 + 1] = acc1 * inv;
    }
#pragma unroll
    for (int i = 0; i < 4; i++) {
        int lin = t + i*256;
        *(float4*)&sm[AKV + lin*4]        = *(const float4*)(wo  + lin*4);
        *(float4*)&sm[AKV + 4096 + lin*4] = *(const float4*)(aw1 + lin*4);
    }
    __syncthreads();

    {
        int c = lane * 2;
        float2 bov = *(const float2*)&bo[c];
        float f0 = bov.x, f1 = bov.y;
#pragma unroll 8
        for (int j = 0; j < 64; j++) {
            float s = sm[ACS + w*64 + j];
            float2 ww = *(const float2*)&sm[AKV + j*64 + c];
            f0 += s*ww.x; f1 += s*ww.y;
        }
        sm[ATF + w*64 + c] = f0; sm[ATF + w*64 + c + 1] = f1;
        __syncwarp();
        float2 abv = *(const float2*)&ab1[c];
        float p0 = abv.x, p1 = abv.y;
#pragma unroll 8
        for (int j = 0; j < 64; j++) {
            float s = sm[ATF + w*64 + j];
            float2 ww = *(const float2*)&sm[AKV + 4096 + j*64 + c];
            p0 += s*ww.x; p1 += s*ww.y;
        }
        *(float2*)&g_tp[(size_t)(b*128 + tk0 + w)*64 + c] = make_float2(p0, p1);
    }
}

// =====================================================================
// Kernel 4 (dominant): pairwise MLP + softmax. block per (b,t), 128 thr
// ROW-MAJOR h1s (proven 201us design), widened thread tile 4 rows x 16
// cols so each pack2 feeds 8 fma2 (instr/fma2: 1.75 -> 1.28).
// 2 tiles of 256 robots. NO min-blocks clause.
// smem (floats): W2 0(2048) | b2 2048(32) | w3 2080(32) | tp 2112(64)
//   h1s 2176(256*68=17408) | sp 19584(2*260=520) | sc 20104(512)
//   red 20616(8)  total 20624 fl = 82496 B
// =====================================================================
#define SW2  0
#define SB2  2048
#define SW3  2080
#define STP  2112
#define SH1  2176
#define SSP  19584
#define SSC  20104
#define SRED 20616
#define PAIR_SMEM_FLOATS 20624

__global__ void __launch_bounds__(128) k_pair(
    const float* __restrict__ aw2, const float* __restrict__ ab2,
    const float* __restrict__ aw3, float* __restrict__ out)
{
    extern __shared__ float sm[];
    int bt = blockIdx.x;
    int b  = bt >> 7;
    int t = threadIdx.x, lane = t & 31, wid = t >> 5;

    for (int i = t; i < 2048; i += 128) sm[SW2 + i] = aw2[i];
    if (t < 32) { sm[SB2 + t] = ab2[t]; sm[SW3 + t] = aw3[t]; }
    if (t < 64) sm[STP + t] = g_tp[bt*64 + t];
    __syncthreads();

    int tx = t & 1;          // col group: cols tx*16 .. +15 (8 col pairs)
    int ty = t >> 1;         // 0..63 -> rows ty + 64m, m=0..3
    int j4b = t & 15;        // build: fixed column quad per thread
    int rrb = t >> 4;        // build: base row (0..7)
    const float* rpb = g_rp + (size_t)b*RR*64;
    float4 tv = *(const float4*)&sm[STP + j4b*4];

    for (int tile = 0; tile < 2; tile++) {
        int r0 = tile * 256;
        // ---- build h1s[rr][j]: relu(tp + rp), 256 rows x 64 cols ----
#pragma unroll 8
        for (int i = 0; i < 32; i++) {
            int rr = rrb + i*8;
            float4 rv = *(const float4*)(rpb + (size_t)(r0 + rr)*64 + j4b*4);
            float4 hv;
            hv.x = fmaxf(rv.x + tv.x, 0.f);
            hv.y = fmaxf(rv.y + tv.y, 0.f);
            hv.z = fmaxf(rv.z + tv.z, 0.f);
            hv.w = fmaxf(rv.w + tv.w, 0.f);
            *(float4*)&sm[SH1 + rr*68 + j4b*4] = hv;
        }
        __syncthreads();

        // ---- GEMM: [256 x 32] = h1[256 x 64] @ W2[64 x 32] ----
        ull acc[4][8];
#pragma unroll
        for (int m = 0; m < 4; m++)
#pragma unroll
            for (int cc = 0; cc < 8; cc++)
                acc[m][cc] = *(const ull*)&sm[SB2 + tx*16 + cc*2];

#pragma unroll 4
        for (int j4 = 0; j4 < 16; j4++) {
            float Aa[4][4];
#pragma unroll
            for (int m = 0; m < 4; m++)
                *(float4*)Aa[m] = *(const float4*)&sm[SH1 + (ty + 64*m)*68 + j4*4];
#pragma unroll
            for (int kk = 0; kk < 4; kk++) {
                const ulonglong2* wp = (const ulonglong2*)&sm[SW2 + (j4*4 + kk)*32 + tx*16];
                ulonglong2 w01 = wp[0], w23 = wp[1], w45 = wp[2], w67 = wp[3];
#pragma unroll
                for (int m = 0; m < 4; m++) {
                    ull a2 = pack2(Aa[m][kk]);
                    fma2(acc[m][0], a2, w01.x); fma2(acc[m][1], a2, w01.y);
                    fma2(acc[m][2], a2, w23.x); fma2(acc[m][3], a2, w23.y);
                    fma2(acc[m][4], a2, w45.x); fma2(acc[m][5], a2, w45.y);
                    fma2(acc[m][6], a2, w67.x); fma2(acc[m][7], a2, w67.y);
                }
            }
        }

        // ---- epilogue: relu(h2) . a_w3 (a_b3 cancels in softmax) ----
#pragma unroll
        for (int m = 0; m < 4; m++) {
            float p = 0.f;
#pragma unroll
            for (int cc = 0; cc < 8; cc++) {
                float2 f = unpack2(acc[m][cc]);
                p += fmaxf(f.x, 0.f) * sm[SW3 + tx*16 + 2*cc]
                   + fmaxf(f.y, 0.f) * sm[SW3 + tx*16 + 2*cc + 1];
            }
            sm[SSP + tx*260 + ty + 64*m] = p;
        }
        __syncthreads();
        sm[SSC + r0 + t]       = sm[SSP + t]       + sm[SSP + 260 + t];
        sm[SSC + r0 + t + 128] = sm[SSP + t + 128] + sm[SSP + 260 + t + 128];
        __syncthreads();
    }

    // ---- softmax over 512 robots ----
    float v0 = sm[SSC + t], v1 = sm[SSC + t + 128], v2 = sm[SSC + t + 256], v3 = sm[SSC + t + 384];
    float m = fmaxf(fmaxf(v0, v1), fmaxf(v2, v3));
#pragma unroll
    for (int o = 16; o; o >>= 1) m = fmaxf(m, __shfl_xor_sync(0xffffffffu, m, o));
    if (lane == 0) sm[SRED + wid] = m;
    __syncthreads();
    m = fmaxf(fmaxf(sm[SRED + 0], sm[SRED + 1]), fmaxf(sm[SRED + 2], sm[SRED + 3]));
    v0 = __expf(v0 - m); v1 = __expf(v1 - m); v2 = __expf(v2 - m); v3 = __expf(v3 - m);
    float s = v0 + v1 + v2 + v3;
#pragma unroll
    for (int o = 16; o; o >>= 1) s += __shfl_xor_sync(0xffffffffu, s, o);
    if (lane == 0) sm[SRED + 4 + wid] = s;
    __syncthreads();
    s = sm[SRED + 4] + sm[SRED + 5] + sm[SRED + 6] + sm[SRED + 7];
    float inv = 1.f / s;
    float* op = out + (size_t)bt * 512;
    op[t]     = v0 * inv;
    op[t+128] = v1 * inv;
    op[t+256] = v2 * inv;
    op[t+384] = v3 * inv;
}

// =====================================================================
extern "C" void kernel_launch(void* const* d_in, const int* in_sizes, int n_in,
                              void* d_out, int out_size)
{
    (void)in_sizes; (void)n_in; (void)out_size;
    const float* robot = (const float*)d_in[0];
    const float* task  = (const float*)d_in[1];
    const float* r_w1  = (const float*)d_in[2];
    const float* r_b1  = (const float*)d_in[3];
    const float* r_w2  = (const float*)d_in[4];
    const float* r_b2  = (const float*)d_in[5];
    const float* t_w1  = (const float*)d_in[6];
    const float* t_b1  = (const float*)d_in[7];
    const float* t_w2  = (const float*)d_in[8];
    const float* t_b2  = (const float*)d_in[9];
    const float* wq    = (const float*)d_in[10];
    const float* bq    = (const float*)d_in[11];
    const float* wk    = (const float*)d_in[12];
    const float* bk    = (const float*)d_in[13];
    const float* wv    = (const float*)d_in[14];
    const float* bv    = (const float*)d_in[15];
    const float* wo    = (const float*)d_in[16];
    const float* bo    = (const float*)d_in[17];
    const float* a_w1  = (const float*)d_in[18];
    const float* a_b1  = (const float*)d_in[19];
    const float* a_w2  = (const float*)d_in[20];
    const float* a_b2  = (const float*)d_in[21];
    const float* a_w3  = (const float*)d_in[22];

    static_assert(ATTN_SMEM_FLOATS * 4 < 230000, "attn smem");
    static_assert(PAIR_SMEM_FLOATS * 4 < 114000, "pair smem (2 CTA/SM)");
    cudaFuncSetAttribute(k_attn, cudaFuncAttributeMaxDynamicSharedMemorySize, ATTN_SMEM_FLOATS * 4);
    cudaFuncSetAttribute(k_pair, cudaFuncAttributeMaxDynamicSharedMemorySize, PAIR_SMEM_FLOATS * 4);

    k_enc <<<1024, 256>>>(robot, task, r_w1, r_b1, r_w2, r_b2,
                          t_w1, t_b1, t_w2, t_b2, wq, bq, wk, bk, wv, bv, a_w1);
    k_attn<<<BB*16, 256, ATTN_SMEM_FLOATS * 4>>>(wo, bo, a_w1, a_b1);
    k_pair<<<BB*TT, 128, PAIR_SMEM_FLOATS * 4>>>(a_w2, a_b2, a_w3, (float*)d_out);
}